// round 13
// baseline (speedup 1.0000x reference)
#include <cuda_runtime.h>
#include <cuda_fp16.h>
#include <math.h>
#include <stdint.h>

// Problem constants
#define BB   2
#define TT   2048
#define DIM  1024
#define NH   16
#define DK   64
#define TOPK 64
#define HID  8192
#define M_ROWS (BB*TT)           // 4096
#define NBH  (BB*NH)             // 32

// ---------------- scratch ------------------------------------------------------
__device__ __half g_xn  [(size_t)M_ROWS * DIM];
__device__ __half g_qkv [(size_t)M_ROWS * 3 * DIM];
__device__ __half g_S   [(size_t)NBH * TT * TT];
__device__ __half g_vt  [(size_t)NBH * DK * TT];
__device__ __half g_attn[(size_t)M_ROWS * DIM];
__device__ float  g_x1  [(size_t)M_ROWS * DIM];
__device__ __half g_xn2 [(size_t)M_ROWS * DIM];
__device__ __half g_h   [(size_t)M_ROWS * HID];
__device__ __half g_wqkvT[(size_t)3 * DIM * DIM];
__device__ __half g_woutT[(size_t)DIM * DIM];
__device__ __half g_w1T  [(size_t)HID * DIM];
__device__ __half g_w2T  [(size_t)DIM * HID];
// per-row softmax params: (m, cd, cs, thr-bits) + cutoff column
__device__ float4 g_rp0 [(size_t)NBH * TT];
__device__ int    g_rp1 [(size_t)NBH * TT];

// ---------------- helpers ------------------------------------------------------
__device__ __forceinline__ void hmma(float* c, const unsigned* a, const unsigned b0,
                                     const unsigned b1)
{
    asm volatile(
        "mma.sync.aligned.m16n8k16.row.col.f32.f16.f16.f32 "
        "{%0,%1,%2,%3},{%4,%5,%6,%7},{%8,%9},{%0,%1,%2,%3};\n"
        : "+f"(c[0]), "+f"(c[1]), "+f"(c[2]), "+f"(c[3])
        : "r"(a[0]), "r"(a[1]), "r"(a[2]), "r"(a[3]), "r"(b0), "r"(b1));
}
__device__ __forceinline__ void ldsm_x4(unsigned* r, unsigned saddr)
{
    asm volatile("ldmatrix.sync.aligned.m8n8.x4.shared.b16 {%0,%1,%2,%3}, [%4];"
                 : "=r"(r[0]), "=r"(r[1]), "=r"(r[2]), "=r"(r[3]) : "r"(saddr));
}
__device__ __forceinline__ void ldsm_x2(unsigned* r, unsigned saddr)
{
    asm volatile("ldmatrix.sync.aligned.m8n8.x2.shared.b16 {%0,%1}, [%2];"
                 : "=r"(r[0]), "=r"(r[1]) : "r"(saddr));
}
__device__ __forceinline__ void cp16s(unsigned saddr, const void* g)
{
    asm volatile("cp.async.cg.shared.global [%0], [%1], 16;\n" :: "r"(saddr), "l"(g));
}
#define CP_COMMIT() asm volatile("cp.async.commit_group;\n")

__device__ __forceinline__ unsigned ordkey16(unsigned h)
{
    return (h & 0x8000u) ? (~h & 0xFFFFu) : (h | 0x8000u);
}
__device__ __forceinline__ float ordkey16_inv(unsigned k)
{
    unsigned short hb = (unsigned short)((k & 0x8000u) ? (k & 0x7FFFu) : (~k & 0xFFFFu));
    __half hv = __ushort_as_half(hb);
    return __half2float(hv);
}

// ---------------- weight transpose fp32 -> half [C][R] (64x64 tiles) ------------
__global__ __launch_bounds__(256)
void trk(const float* __restrict__ src, __half* __restrict__ dst, int R, int C)
{
    __shared__ float t[64][65];
    const int c0 = blockIdx.x * 64, r0 = blockIdx.y * 64;
    const int tid = threadIdx.x;
    // read 64x64 floats: 1024 float4, 4 per thread
#pragma unroll
    for (int j = 0; j < 4; j++) {
        int idx = tid + j * 256;
        int row = idx >> 4, c4 = (idx & 15) << 2;
        float4 v = *(const float4*)(src + (size_t)(r0 + row) * C + c0 + c4);
        t[row][c4 + 0] = v.x; t[row][c4 + 1] = v.y;
        t[row][c4 + 2] = v.z; t[row][c4 + 3] = v.w;
    }
    __syncthreads();
    // write 64 dst-rows x 64 halves: 512 uint4, 2 per thread
#pragma unroll
    for (int j = 0; j < 2; j++) {
        int idx = tid + j * 256;
        int drow = idx >> 3, seg = (idx & 7) << 3;   // source col = drow, rows seg..seg+7
        __half hs[8];
#pragma unroll
        for (int k = 0; k < 8; k++)
            hs[k] = __float2half_rn(t[seg + k][drow]);
        *(uint4*)(dst + (size_t)(c0 + drow) * R + r0 + seg) = *(uint4*)hs;
    }
}

// ---------------- V transpose: qkv half -> vt[bh][d][t] -------------------------
__global__ __launch_bounds__(256)
void vtrans(const __half* __restrict__ qkv, __half* __restrict__ vt)
{
    __shared__ __half t[32][33];
    const int bh = blockIdx.z, b = bh >> 4, h = bh & 15;
    const int t0 = blockIdx.x * 32, d0 = blockIdx.y * 32;
    const int x = threadIdx.x, y = threadIdx.y;
#pragma unroll
    for (int j = 0; j < 32; j += 8)
        t[y + j][x] = qkv[(size_t)(b * TT + t0 + y + j) * (3 * DIM) + 2 * DIM + h * DK + d0 + x];
    __syncthreads();
#pragma unroll
    for (int j = 0; j < 32; j += 8)
        vt[((size_t)bh * DK + d0 + y + j) * TT + t0 + x] = t[x][y + j];
}

// ---------------- LayerNorm (half output) ---------------------------------------
__global__ __launch_bounds__(256)
void ln_kernel(const float* __restrict__ x, const float* __restrict__ g,
               const float* __restrict__ b, __half* __restrict__ o)
{
    const int rowbase = blockIdx.x * DIM;
    const int tid = threadIdx.x;
    float v[4];
    float s = 0.f, s2 = 0.f;
#pragma unroll
    for (int i = 0; i < 4; i++) {
        v[i] = x[rowbase + tid + i * 256];
        s  += v[i];
        s2 += v[i] * v[i];
    }
    __shared__ float r1[256], r2[256];
    r1[tid] = s; r2[tid] = s2; __syncthreads();
    for (int st = 128; st > 0; st >>= 1) {
        if (tid < st) { r1[tid] += r1[tid + st]; r2[tid] += r2[tid + st]; }
        __syncthreads();
    }
    const float mu   = r1[0] * (1.f / DIM);
    const float var  = r2[0] * (1.f / DIM) - mu * mu;
    const float rstd = rsqrtf(var + 1e-5f);
#pragma unroll
    for (int i = 0; i < 4; i++) {
        int c = tid + i * 256;
        o[rowbase + c] = __float2half_rn((v[i] - mu) * rstd * g[c] + b[c]);
    }
}

// ---------------- fp16 pipelined GEMM (R10: BK=64, 2-stage, warp 64x32) ---------
#define H_LDW 72
#define H_TILEW (128*H_LDW)
#define H_SMEM (2*2*H_TILEW*2)

template <int EPI>
__global__ __launch_bounds__(256, 2)
void hgemm(int K,
           const __half* __restrict__ A, int lda,
           const __half* __restrict__ Bt,
           void* __restrict__ Cv, int ldc,
           const float* __restrict__ bias,
           const float* __restrict__ resid,
           const float* __restrict__ alphap)
{
    constexpr bool HOUT = (EPI == 0 || EPI == 2);
    extern __shared__ __half smh[];
    const unsigned sbase = (unsigned)__cvta_generic_to_shared(smh);

    const int tid = threadIdx.x, lane = tid & 31, warp = tid >> 5;
    const int g = lane >> 2, tq = lane & 3;
    const int bm = blockIdx.y * 128, bn = blockIdx.x * 128;
    const int wm = (warp >> 2) * 64, wn = (warp & 3) * 32;

    const unsigned aoff = ((unsigned)((lane & 15) * H_LDW) + ((lane >> 4) << 3)) * 2;
    const unsigned boff = ((unsigned)((lane & 7) * H_LDW) + (((lane >> 3) & 1) << 3)) * 2;

    float acc[4][4][4];
#pragma unroll
    for (int mi = 0; mi < 4; mi++)
#pragma unroll
        for (int ni = 0; ni < 4; ni++)
#pragma unroll
            for (int q = 0; q < 4; q++) acc[mi][ni][q] = 0.f;

    auto load_stage = [&](int i) {
        const int s = i & 1;
        const unsigned sA = sbase + (unsigned)(s * 2 * H_TILEW * 2);
        const unsigned sB = sA + (unsigned)(H_TILEW * 2);
        const __half* Ap = A + (size_t)bm * lda + i * 64;
        const __half* Bp = Bt + (size_t)bn * K + i * 64;
#pragma unroll
        for (int j = 0; j < 4; j++) {
            int idx = tid + j * 256;
            int row = idx >> 3, segh = (idx & 7) << 3;
            cp16s(sA + row * 144 + segh * 2, Ap + (size_t)row * lda + segh);
            cp16s(sB + row * 144 + segh * 2, Bp + (size_t)row * K + segh);
        }
        CP_COMMIT();
    };

    const int KT = K / 64;
    load_stage(0);

    for (int kt = 0; kt < KT; kt++) {
        asm volatile("cp.async.wait_group 0;\n" ::: "memory");
        __syncthreads();
        if (kt + 1 < KT) load_stage(kt + 1);

        const int s = kt & 1;
        const unsigned aStage = sbase + (unsigned)(s * 2 * H_TILEW * 2);
        const unsigned bStage = aStage + (unsigned)(H_TILEW * 2);
#pragma unroll
        for (int ks = 0; ks < 4; ks++) {
            const unsigned kbb = (unsigned)(ks * 32);
            unsigned af[4][4], bf[4][2];
#pragma unroll
            for (int mi = 0; mi < 4; mi++)
                ldsm_x4(af[mi], aStage + (unsigned)((wm + mi * 16) * 144) + aoff + kbb);
#pragma unroll
            for (int ni = 0; ni < 4; ni++)
                ldsm_x2(bf[ni], bStage + (unsigned)((wn + ni * 8) * 144) + boff + kbb);
#pragma unroll
            for (int mi = 0; mi < 4; mi++)
#pragma unroll
                for (int ni = 0; ni < 4; ni++)
                    hmma(acc[mi][ni], af[mi], bf[ni][0], bf[ni][1]);
        }
    }

    const float al = (EPI == 1 || EPI == 3) ? alphap[0] : 0.f;
#pragma unroll
    for (int mi = 0; mi < 4; mi++) {
#pragma unroll
        for (int ni = 0; ni < 4; ni++) {
            int r0 = bm + wm + mi * 16 + g;
            int c  = bn + wn + ni * 8 + 2 * tq;
#pragma unroll
            for (int half = 0; half < 2; half++) {
                int r = r0 + half * 8;
                size_t off = (size_t)r * ldc + c;
                float v0 = acc[mi][ni][half * 2];
                float v1 = acc[mi][ni][half * 2 + 1];
                float o0, o1;
                if (EPI == 0) {
                    o0 = v0; o1 = v1;
                } else if (EPI == 1) {
                    o0 = resid[off] + al * v0;
                    o1 = resid[off + 1] + al * v1;
                } else if (EPI == 2) {
                    float u0 = v0 + bias[c], u1 = v1 + bias[c + 1];
                    o0 = 0.5f * u0 * (1.f + erff(u0 * 0.70710678118654752440f));
                    o1 = 0.5f * u1 * (1.f + erff(u1 * 0.70710678118654752440f));
                } else {
                    o0 = resid[off] + al * (v0 + bias[c]);
                    o1 = resid[off + 1] + al * (v1 + bias[c + 1]);
                }
                if (HOUT) {
                    *(__half2*)((__half*)Cv + off) = __floats2half2_rn(o0, o1);
                } else {
                    *(float2*)((float*)Cv + off) = make_float2(o0, o1);
                }
            }
        }
    }
}

// ---------------- batched QK^T (fp16 MMA + ldmatrix): S = Q @ K^T / 8 -> fp16 ---
__global__ __launch_bounds__(256)
void hqk(const __half* __restrict__ qkv, __half* __restrict__ S)
{
    __shared__ __half As[128][72];
    __shared__ __half Bs[128][72];

    const int bh = blockIdx.z, b = bh >> 4, h = bh & 15;
    const __half* Q  = qkv + (size_t)b * TT * (3 * DIM) + h * DK;
    const __half* Kp = qkv + (size_t)b * TT * (3 * DIM) + DIM + h * DK;
    __half* Sp = S + (size_t)bh * TT * TT;

    const int tid = threadIdx.x, lane = tid & 31, warp = tid >> 5;
    const int g = lane >> 2, tq = lane & 3;
    const int bm = blockIdx.y * 128, bn = blockIdx.x * 128;
    const int wm = (warp >> 2) * 64, wn = (warp & 3) * 32;

    const unsigned sA = (unsigned)__cvta_generic_to_shared(&As[0][0]);
    const unsigned sB = (unsigned)__cvta_generic_to_shared(&Bs[0][0]);
    const unsigned aoff = ((unsigned)((lane & 15) * 72) + ((lane >> 4) << 3)) * 2;
    const unsigned boff = ((unsigned)((lane & 7) * 72) + (((lane >> 3) & 1) << 3)) * 2;

    float acc[4][4][4];
#pragma unroll
    for (int mi = 0; mi < 4; mi++)
#pragma unroll
        for (int ni = 0; ni < 4; ni++)
#pragma unroll
            for (int q = 0; q < 4; q++) acc[mi][ni][q] = 0.f;

#pragma unroll
    for (int j = 0; j < 4; j++) {
        int idx = tid + j * 256;
        int m = idx >> 3, seg = (idx & 7) << 3;
        *(uint4*)&As[m][seg] = *(const uint4*)(Q  + (size_t)(bm + m) * (3 * DIM) + seg);
        *(uint4*)&Bs[m][seg] = *(const uint4*)(Kp + (size_t)(bn + m) * (3 * DIM) + seg);
    }
    __syncthreads();

#pragma unroll
    for (int ks = 0; ks < 4; ks++) {
        const unsigned kbb = (unsigned)(ks * 32);
        unsigned af[4][4], bf[4][2];
#pragma unroll
        for (int mi = 0; mi < 4; mi++)
            ldsm_x4(af[mi], sA + (unsigned)((wm + mi * 16) * 144) + aoff + kbb);
#pragma unroll
        for (int ni = 0; ni < 4; ni++)
            ldsm_x2(bf[ni], sB + (unsigned)((wn + ni * 8) * 144) + boff + kbb);
#pragma unroll
        for (int mi = 0; mi < 4; mi++)
#pragma unroll
            for (int ni = 0; ni < 4; ni++)
                hmma(acc[mi][ni], af[mi], bf[ni][0], bf[ni][1]);
    }

#pragma unroll
    for (int mi = 0; mi < 4; mi++)
#pragma unroll
        for (int ni = 0; ni < 4; ni++) {
            int r0 = bm + wm + mi * 16 + g;
            int c  = bn + wn + ni * 8 + 2 * tq;
#pragma unroll
            for (int half = 0; half < 2; half++) {
                size_t off = (size_t)(r0 + half * 8) * TT + c;
                *(__half2*)(Sp + off) = __floats2half2_rn(acc[mi][ni][half * 2] * 0.125f,
                                                          acc[mi][ni][half * 2 + 1] * 0.125f);
            }
        }
}

// ---------------- stats-only dual softmax + exact top-64 ------------------------
__global__ __launch_bounds__(256)
void softmax_stats(const __half* __restrict__ S,
                   float4* __restrict__ rp0, int* __restrict__ rp1,
                   const float* __restrict__ alpha_head)
{
    __shared__ int   hist[256];
    __shared__ int   chunkeq[256];
    __shared__ int   chunkpre[256];
    __shared__ float rmax[8];
    __shared__ int   wri[8];
    __shared__ float wrf1[8], wrf2[8];
    __shared__ unsigned selb;
    __shared__ int   selc;
    __shared__ int   cutoff_sh;

    const int tid = threadIdx.x, lane = tid & 31, w = tid >> 5;
    const int rowid = blockIdx.x;
    const int h = (rowid >> 11) & 15;
    const __half* row = S + (size_t)rowid * TT;

    if (tid == 0) cutoff_sh = TT;

    uint4 pk = *(const uint4*)(row + tid * 8);
    unsigned hw[4] = {pk.x, pk.y, pk.z, pk.w};
    float v[8];
    unsigned u[8];
    float m = -3.4e38f;
#pragma unroll
    for (int i = 0; i < 4; i++) {
        unsigned lo = hw[i] & 0xFFFFu, hi = hw[i] >> 16;
        v[2 * i]     = __half2float(__ushort_as_half((unsigned short)lo));
        v[2 * i + 1] = __half2float(__ushort_as_half((unsigned short)hi));
        u[2 * i]     = ordkey16(lo);
        u[2 * i + 1] = ordkey16(hi);
    }
#pragma unroll
    for (int i = 0; i < 8; i++) m = fmaxf(m, v[i]);
#pragma unroll
    for (int o = 16; o > 0; o >>= 1) m = fmaxf(m, __shfl_xor_sync(0xFFFFFFFFu, m, o));
    if (lane == 0) rmax[w] = m;
    __syncthreads();
#pragma unroll
    for (int j = 0; j < 8; j++) m = fmaxf(m, rmax[j]);

    unsigned prefix = 0u, pmask = 0u;
    int kth = TOPK;
#pragma unroll
    for (int shift = 8; shift >= 0; shift -= 8) {
        hist[tid] = 0;
        __syncthreads();
#pragma unroll
        for (int i = 0; i < 8; i++)
            if ((u[i] & pmask) == prefix) atomicAdd(&hist[(u[i] >> shift) & 255], 1);
        __syncthreads();
        if (w == 0) {
            const int base = lane * 8;
            int hv[8], loc[8];
            int s = 0;
#pragma unroll
            for (int j = 7; j >= 0; j--) { hv[j] = hist[base + j]; s += hv[j]; loc[j] = s; }
            int suf = s;
#pragma unroll
            for (int o = 1; o < 32; o <<= 1) {
                int t = __shfl_down_sync(0xFFFFFFFFu, suf, o);
                if (lane + o < 32) suf += t;
            }
            const int higher = suf - s;
            int cand = -1, cabove = 0;
#pragma unroll
            for (int j = 7; j >= 0; j--) {
                int cum = higher + loc[j];
                if (cum >= kth) { cand = base + j; cabove = cum - hv[j]; break; }
            }
#pragma unroll
            for (int o = 16; o > 0; o >>= 1) {
                int oc = __shfl_xor_sync(0xFFFFFFFFu, cand, o);
                int oa = __shfl_xor_sync(0xFFFFFFFFu, cabove, o);
                if (oc > cand) { cand = oc; cabove = oa; }
            }
            if (lane == 0) { selb = (unsigned)cand; selc = cabove; }
        }
        __syncthreads();
        prefix |= selb << shift;
        pmask  |= 0xFFu << shift;
        kth    -= selc;
        __syncthreads();
    }
    const unsigned thr = prefix;

    float e[8];
    float sd = 0.f, sgt = 0.f;
    int cgt = 0, ceq = 0;
#pragma unroll
    for (int i = 0; i < 8; i++) {
        e[i] = __expf(v[i] - m);
        sd += e[i];
        if (u[i] > thr) { cgt++; sgt += e[i]; }
        else if (u[i] == thr) ceq++;
    }
    chunkeq[tid] = ceq;
#pragma unroll
    for (int o = 16; o > 0; o >>= 1) {
        sd  += __shfl_xor_sync(0xFFFFFFFFu, sd, o);
        sgt += __shfl_xor_sync(0xFFFFFFFFu, sgt, o);
        cgt += __shfl_xor_sync(0xFFFFFFFFu, cgt, o);
    }
    if (lane == 0) { wri[w] = cgt; wrf1[w] = sd; wrf2[w] = sgt; }
    __syncthreads();
    int n_gt = 0; float Zd = 0.f, Sgt = 0.f;
#pragma unroll
    for (int j = 0; j < 8; j++) { n_gt += wri[j]; Zd += wrf1[j]; Sgt += wrf2[j]; }

    const int need = TOPK - n_gt;
    const float ethr = __expf(ordkey16_inv(thr) - m);
    const float Zs = Sgt + (float)need * ethr;

    if (w == 0) {
        const int base = lane * 8;
        int c[8], loc[8];
        int ex = 0;
#pragma unroll
        for (int j = 0; j < 8; j++) { c[j] = chunkeq[base + j]; loc[j] = ex; ex += c[j]; }
        int acc = ex;
#pragma unroll
        for (int o = 1; o < 32; o <<= 1) {
            int t = __shfl_up_sync(0xFFFFFFFFu, acc, o);
            if (lane >= o) acc += t;
        }
        const int wex = acc - ex;
#pragma unroll
        for (int j = 0; j < 8; j++) chunkpre[base + j] = wex + loc[j];
    }
    __syncthreads();

    // cutoff column = column of the need-th tie (first EXCLUDED tie); TT if none
    {
        int tierank = chunkpre[tid];
#pragma unroll
        for (int i = 0; i < 8; i++) {
            if (u[i] == thr) {
                if (tierank == need) cutoff_sh = tid * 8 + i;  // unique writer
                tierank++;
            }
        }
    }
    __syncthreads();

    if (tid == 0) {
        const float gate = 1.f / (1.f + __expf(-alpha_head[h]));
        rp0[rowid] = make_float4(m, gate / Zd, (1.f - gate) / Zs, __uint_as_float(thr));
        rp1[rowid] = cutoff_sh;
    }
}

// ---------------- batched PV with inline S->P conversion ------------------------
#define PV_AW (128*72)
#define PV_BW (64*72)
#define PV_SMEM (2*(PV_AW+PV_BW)*2)       // 55296 bytes (dynamic; table is static)

__global__ __launch_bounds__(256, 2)
void hpv(const __half* __restrict__ S, const __half* __restrict__ Vt,
         const float4* __restrict__ rp0, const int* __restrict__ rp1,
         __half* __restrict__ attn_out)
{
    extern __shared__ __half smh[];
    const unsigned sbase = (unsigned)__cvta_generic_to_shared(smh);
    __shared__ float4 rps[128];
    __shared__ int    rcut[128];

    const int bh = blockIdx.y, b = bh >> 4, h = bh & 15;
    const __half* Sp = S + (size_t)bh * TT * TT;
    const __half* Vp = Vt + (size_t)bh * DK * TT;

    const int tid = threadIdx.x, lane = tid & 31, warp = tid >> 5;
    const int g = lane >> 2, tq = lane & 3;
    const int bm = blockIdx.x * 128;
    const int wm = (warp >> 1) * 32, wn = (warp & 1) * 32;

    const unsigned aoff = ((unsigned)((lane & 15) * 72) + ((lane >> 4) << 3)) * 2;
    const unsigned boff = ((unsigned)((lane & 7) * 72) + (((lane >> 3) & 1) << 3)) * 2;

    if (tid < 128) {
        rps[tid]  = rp0[(size_t)bh * TT + bm + tid];
        rcut[tid] = rp1[(size_t)bh * TT + bm + tid];
    }

    float acc[2][4][4];
#pragma unroll
    for (int mi = 0; mi < 2; mi++)
#pragma unroll
        for (int ni = 0; ni < 4; ni++)
#pragma unroll
            for (int q = 0; q < 4; q++) acc[mi][ni][q] = 0.f;

    auto loadV = [&](int i) {
        const int s = i & 1;
        const unsigned sB = sbase + (unsigned)((s * (PV_AW + PV_BW) + PV_AW) * 2);
        const __half* Bp = Vp + i * 64;
#pragma unroll
        for (int j = 0; j < 2; j++) {
            int idx = tid + j * 256;
            int row = idx >> 3, segh = (idx & 7) << 3;
            cp16s(sB + row * 144 + segh * 2, Bp + (size_t)row * TT + segh);
        }
        CP_COMMIT();
    };
    auto ldA = [&](int i, uint4* araw) {
#pragma unroll
        for (int j = 0; j < 4; j++) {
            int idx = tid + j * 256;
            int row = idx >> 3, segh = (idx & 7) << 3;
            araw[j] = *(const uint4*)(Sp + (size_t)(bm + row) * TT + i * 64 + segh);
        }
    };
    auto cvtStore = [&](int i, const uint4* araw) {
        const int s = i & 1;
        const unsigned sA = sbase + (unsigned)(s * (PV_AW + PV_BW) * 2);
#pragma unroll
        for (int j = 0; j < 4; j++) {
            int idx = tid + j * 256;
            int row = idx >> 3, segh = (idx & 7) << 3;
            float4 rp = rps[row];
            const float m = rp.x, cd = rp.y, cs = rp.z;
            const unsigned thr = __float_as_uint(rp.w);
            const int cut = rcut[row];
            const int col0 = i * 64 + segh;
            unsigned hw[4] = {araw[j].x, araw[j].y, araw[j].z, araw[j].w};
            __half hs[8];
#pragma unroll
            for (int q = 0; q < 4; q++) {
                unsigned lo = hw[q] & 0xFFFFu, hi = hw[q] >> 16;
                float f0 = __half2float(__ushort_as_half((unsigned short)lo));
                float f1 = __half2float(__ushort_as_half((unsigned short)hi));
                unsigned u0 = ordkey16(lo), u1 = ordkey16(hi);
                int c0 = col0 + 2 * q, c1 = c0 + 1;
                bool i0 = (u0 > thr) || (u0 == thr && c0 < cut);
                bool i1 = (u1 > thr) || (u1 == thr && c1 < cut);
                float e0 = __expf(f0 - m), e1 = __expf(f1 - m);
                hs[2 * q]     = __float2half_rn(e0 * (cd + (i0 ? cs : 0.f)));
                hs[2 * q + 1] = __float2half_rn(e1 * (cd + (i1 ? cs : 0.f)));
            }
            unsigned dst = sA + row * 144 + segh * 2;
            asm volatile("st.shared.v4.b32 [%0], {%1,%2,%3,%4};\n"
                         :: "r"(dst), "r"(((unsigned*)hs)[0]), "r"(((unsigned*)hs)[1]),
                            "r"(((unsigned*)hs)[2]), "r"(((unsigned*)hs)[3]));
        }
    };

    const int KT = TT / 64;
    uint4 araw[4];
    loadV(0);
    ldA(0, araw);
    __syncthreads();           // rps table ready
    cvtStore(0, araw);
    asm volatile("cp.async.wait_group 0;\n" ::: "memory");
    __syncthreads();

    for (int kt = 0; kt < KT; kt++) {
        if (kt + 1 < KT) {
            ldA(kt + 1, araw);
            loadV(kt + 1);
        }

        const int s = kt & 1;
        const unsigned aStage = sbase + (unsigned)(s * (PV_AW + PV_BW) * 2);
        const unsigned bStage = aStage + (unsigned)(PV_AW * 2);
#pragma unroll
        for (int ks = 0; ks < 4; ks++) {
            const unsigned kbb = (unsigned)(ks * 32);
            unsigned af[2][4], bf[4][2];
#pragma unroll
            for (int mi = 0; mi < 2; mi++)
                ldsm_x4(af[mi], aStage + (unsigned)((wm + mi * 16) * 144) + aoff + kbb);
#pragma unroll
            for (int ni = 0; ni < 4; ni++)
                ldsm_x2(bf[ni], bStage + (unsigned)((wn + ni * 8) * 144) + boff + kbb);
#pragma unroll
            for (int mi = 0; mi < 2; mi++)
#pragma unroll
                for (int ni = 0; ni < 4; ni++)
                    hmma(acc[mi][ni], af[mi], bf[ni][0], bf[ni][1]);
        }

        if (kt + 1 < KT) {
            cvtStore(kt + 1, araw);
            asm volatile("cp.async.wait_group 0;\n" ::: "memory");
        }
        __syncthreads();
    }

#pragma unroll
    for (int mi = 0; mi < 2; mi++)
#pragma unroll
        for (int ni = 0; ni < 4; ni++) {
            int r0 = bm + wm + mi * 16 + g;
            int c  = wn + ni * 8 + 2 * tq;
#pragma unroll
            for (int half = 0; half < 2; half++) {
                int r = r0 + half * 8;
                size_t off = (size_t)(b * TT + r) * DIM + h * DK + c;
                *(__half2*)(attn_out + off) =
                    __floats2half2_rn(acc[mi][ni][half * 2], acc[mi][ni][half * 2 + 1]);
            }
        }
}

// ---------------- launch --------------------------------------------------------
extern "C" void kernel_launch(void* const* d_in, const int* in_sizes, int n_in,
                              void* d_out, int out_size)
{
    const float* x          = (const float*)d_in[0];
    const float* ln1_g      = (const float*)d_in[1];
    const float* ln1_b      = (const float*)d_in[2];
    const float* w_qkv      = (const float*)d_in[3];
    const float* alpha_head = (const float*)d_in[4];
    const float* w_out      = (const float*)d_in[5];
    const float* ln2_g      = (const float*)d_in[6];
    const float* ln2_b      = (const float*)d_in[7];
    const float* w1         = (const float*)d_in[8];
    const float* b1         = (const float*)d_in[9];
    const float* w2         = (const float*)d_in[10];
    const float* b2         = (const float*)d_in[11];
    const float* alpha      = (const float*)d_in[12];
    float* out = (float*)d_out;

    __half *xn, *qkv, *Sm, *vt, *attn, *xn2, *hbuf, *wqkvT, *woutT, *w1T, *w2T;
    float *x1;
    float4 *rp0;
    int *rp1;
    cudaGetSymbolAddress((void**)&xn,    g_xn);
    cudaGetSymbolAddress((void**)&qkv,   g_qkv);
    cudaGetSymbolAddress((void**)&Sm,    g_S);
    cudaGetSymbolAddress((void**)&vt,    g_vt);
    cudaGetSymbolAddress((void**)&attn,  g_attn);
    cudaGetSymbolAddress((void**)&x1,    g_x1);
    cudaGetSymbolAddress((void**)&xn2,   g_xn2);
    cudaGetSymbolAddress((void**)&hbuf,  g_h);
    cudaGetSymbolAddress((void**)&wqkvT, g_wqkvT);
    cudaGetSymbolAddress((void**)&woutT, g_woutT);
    cudaGetSymbolAddress((void**)&w1T,   g_w1T);
    cudaGetSymbolAddress((void**)&w2T,   g_w2T);
    cudaGetSymbolAddress((void**)&rp0,   g_rp0);
    cudaGetSymbolAddress((void**)&rp1,   g_rp1);

    cudaFuncSetAttribute(hgemm<0>, cudaFuncAttributeMaxDynamicSharedMemorySize, H_SMEM);
    cudaFuncSetAttribute(hgemm<1>, cudaFuncAttributeMaxDynamicSharedMemorySize, H_SMEM);
    cudaFuncSetAttribute(hgemm<2>, cudaFuncAttributeMaxDynamicSharedMemorySize, H_SMEM);
    cudaFuncSetAttribute(hgemm<3>, cudaFuncAttributeMaxDynamicSharedMemorySize, H_SMEM);
    cudaFuncSetAttribute(hpv, cudaFuncAttributeMaxDynamicSharedMemorySize, PV_SMEM);

    trk<<<dim3(3*DIM/64, DIM/64), 256>>>(w_qkv, wqkvT, DIM, 3*DIM);
    trk<<<dim3(DIM/64,   DIM/64), 256>>>(w_out, woutT, DIM, DIM);
    trk<<<dim3(HID/64,   DIM/64), 256>>>(w1,    w1T,   DIM, HID);
    trk<<<dim3(DIM/64,   HID/64), 256>>>(w2,    w2T,   HID, DIM);

    ln_kernel<<<M_ROWS, 256>>>(x, ln1_g, ln1_b, xn);
    hgemm<0><<<dim3(3*DIM/128, M_ROWS/128), 256, H_SMEM>>>(
        DIM, xn, DIM, wqkvT, qkv, 3*DIM, nullptr, nullptr, nullptr);
    hqk<<<dim3(TT/128, TT/128, NBH), 256>>>(qkv, Sm);
    vtrans<<<dim3(TT/32, DK/32, NBH), dim3(32,8)>>>(qkv, vt);
    softmax_stats<<<NBH*TT, 256>>>(Sm, rp0, rp1, alpha_head);
    hpv<<<dim3(TT/128, NBH), 256, PV_SMEM>>>(Sm, vt, rp0, rp1, attn);
    hgemm<1><<<dim3(DIM/128, M_ROWS/128), 256, H_SMEM>>>(
        DIM, attn, DIM, woutT, x1, DIM, nullptr, x, alpha);
    ln_kernel<<<M_ROWS, 256>>>(x1, ln2_g, ln2_b, xn2);
    hgemm<2><<<dim3(HID/128, M_ROWS/128), 256, H_SMEM>>>(
        DIM, xn2, DIM, w1T, hbuf, HID, b1, nullptr, nullptr);
    hgemm<3><<<dim3(DIM/128, M_ROWS/128), 256, H_SMEM>>>(
        HID, hbuf, HID, w2T, out, DIM, b2, x1, alpha);
}

// round 14
// speedup vs baseline: 1.0601x; 1.0601x over previous
#include <cuda_runtime.h>
#include <cuda_fp16.h>
#include <math.h>
#include <stdint.h>

// Problem constants
#define BB   2
#define TT   2048
#define DIM  1024
#define NH   16
#define DK   64
#define TOPK 64
#define HID  8192
#define M_ROWS (BB*TT)           // 4096
#define NBH  (BB*NH)             // 32

// ---------------- scratch ------------------------------------------------------
__device__ __half g_xn  [(size_t)M_ROWS * DIM];
__device__ __half g_qkv [(size_t)M_ROWS * 3 * DIM];
__device__ __half g_S   [(size_t)NBH * TT * TT];
__device__ __half g_P   [(size_t)NBH * TT * TT];
__device__ __half g_vt  [(size_t)NBH * DK * TT];
__device__ __half g_attn[(size_t)M_ROWS * DIM];
__device__ float  g_x1  [(size_t)M_ROWS * DIM];
__device__ __half g_xn2 [(size_t)M_ROWS * DIM];
__device__ __half g_h   [(size_t)M_ROWS * HID];
__device__ __half g_wqkvT[(size_t)3 * DIM * DIM];
__device__ __half g_woutT[(size_t)DIM * DIM];
__device__ __half g_w1T  [(size_t)HID * DIM];
__device__ __half g_w2T  [(size_t)DIM * HID];

// ---------------- helpers ------------------------------------------------------
__device__ __forceinline__ void hmma(float* c, const unsigned* a, const unsigned b0,
                                     const unsigned b1)
{
    asm volatile(
        "mma.sync.aligned.m16n8k16.row.col.f32.f16.f16.f32 "
        "{%0,%1,%2,%3},{%4,%5,%6,%7},{%8,%9},{%0,%1,%2,%3};\n"
        : "+f"(c[0]), "+f"(c[1]), "+f"(c[2]), "+f"(c[3])
        : "r"(a[0]), "r"(a[1]), "r"(a[2]), "r"(a[3]), "r"(b0), "r"(b1));
}
__device__ __forceinline__ void ldsm_x4(unsigned* r, unsigned saddr)
{
    asm volatile("ldmatrix.sync.aligned.m8n8.x4.shared.b16 {%0,%1,%2,%3}, [%4];"
                 : "=r"(r[0]), "=r"(r[1]), "=r"(r[2]), "=r"(r[3]) : "r"(saddr));
}
__device__ __forceinline__ void ldsm_x2(unsigned* r, unsigned saddr)
{
    asm volatile("ldmatrix.sync.aligned.m8n8.x2.shared.b16 {%0,%1}, [%2];"
                 : "=r"(r[0]), "=r"(r[1]) : "r"(saddr));
}
__device__ __forceinline__ void cp16s(unsigned saddr, const void* g)
{
    asm volatile("cp.async.cg.shared.global [%0], [%1], 16;\n" :: "r"(saddr), "l"(g));
}
#define CP_COMMIT() asm volatile("cp.async.commit_group;\n")

// ---------------- weight transpose fp32 -> half [C][R] (64x64 tiles) ------------
__global__ __launch_bounds__(256)
void trk(const float* __restrict__ src, __half* __restrict__ dst, int R, int C)
{
    __shared__ float t[64][65];
    const int c0 = blockIdx.x * 64, r0 = blockIdx.y * 64;
    const int tid = threadIdx.x;
#pragma unroll
    for (int j = 0; j < 4; j++) {
        int idx = tid + j * 256;
        int row = idx >> 4, c4 = (idx & 15) << 2;
        float4 v = *(const float4*)(src + (size_t)(r0 + row) * C + c0 + c4);
        t[row][c4 + 0] = v.x; t[row][c4 + 1] = v.y;
        t[row][c4 + 2] = v.z; t[row][c4 + 3] = v.w;
    }
    __syncthreads();
#pragma unroll
    for (int j = 0; j < 2; j++) {
        int idx = tid + j * 256;
        int drow = idx >> 3, seg = (idx & 7) << 3;
        __half hs[8];
#pragma unroll
        for (int k = 0; k < 8; k++)
            hs[k] = __float2half_rn(t[seg + k][drow]);
        *(uint4*)(dst + (size_t)(c0 + drow) * R + r0 + seg) = *(uint4*)hs;
    }
}

// ---------------- V transpose: qkv half -> vt[bh][d][t] -------------------------
__global__ __launch_bounds__(256)
void vtrans(const __half* __restrict__ qkv, __half* __restrict__ vt)
{
    __shared__ __half t[32][33];
    const int bh = blockIdx.z, b = bh >> 4, h = bh & 15;
    const int t0 = blockIdx.x * 32, d0 = blockIdx.y * 32;
    const int x = threadIdx.x, y = threadIdx.y;
#pragma unroll
    for (int j = 0; j < 32; j += 8)
        t[y + j][x] = qkv[(size_t)(b * TT + t0 + y + j) * (3 * DIM) + 2 * DIM + h * DK + d0 + x];
    __syncthreads();
#pragma unroll
    for (int j = 0; j < 32; j += 8)
        vt[((size_t)bh * DK + d0 + y + j) * TT + t0 + x] = t[x][y + j];
}

// ---------------- LayerNorm (half output, shuffle reductions) -------------------
__global__ __launch_bounds__(256)
void ln_kernel(const float* __restrict__ x, const float* __restrict__ g,
               const float* __restrict__ b, __half* __restrict__ o)
{
    const int rowbase = blockIdx.x * DIM;
    const int tid = threadIdx.x, lane = tid & 31, w = tid >> 5;
    float v[4];
    float s = 0.f, s2 = 0.f;
#pragma unroll
    for (int i = 0; i < 4; i++) {
        v[i] = x[rowbase + tid + i * 256];
        s  += v[i];
        s2 += v[i] * v[i];
    }
#pragma unroll
    for (int off = 16; off > 0; off >>= 1) {
        s  += __shfl_xor_sync(0xFFFFFFFFu, s, off);
        s2 += __shfl_xor_sync(0xFFFFFFFFu, s2, off);
    }
    __shared__ float ws[8], ws2[8];
    if (lane == 0) { ws[w] = s; ws2[w] = s2; }
    __syncthreads();
    float ts = 0.f, ts2 = 0.f;
#pragma unroll
    for (int j = 0; j < 8; j++) { ts += ws[j]; ts2 += ws2[j]; }
    const float mu   = ts * (1.f / DIM);
    const float var  = ts2 * (1.f / DIM) - mu * mu;
    const float rstd = rsqrtf(var + 1e-5f);
#pragma unroll
    for (int i = 0; i < 4; i++) {
        int c = tid + i * 256;
        o[rowbase + c] = __float2half_rn((v[i] - mu) * rstd * g[c] + b[c]);
    }
}

// ---------------- fp16 pipelined GEMM (R10: BK=64, 2-stage, warp 64x32) ---------
#define H_LDW 72
#define H_TILEW (128*H_LDW)
#define H_SMEM (2*2*H_TILEW*2)

template <int EPI>
__global__ __launch_bounds__(256, 2)
void hgemm(int K,
           const __half* __restrict__ A, int lda,
           const __half* __restrict__ Bt,
           void* __restrict__ Cv, int ldc,
           const float* __restrict__ bias,
           const float* __restrict__ resid,
           const float* __restrict__ alphap)
{
    constexpr bool HOUT = (EPI == 0 || EPI == 2);
    extern __shared__ __half smh[];
    const unsigned sbase = (unsigned)__cvta_generic_to_shared(smh);

    const int tid = threadIdx.x, lane = tid & 31, warp = tid >> 5;
    const int g = lane >> 2, tq = lane & 3;
    const int bm = blockIdx.y * 128, bn = blockIdx.x * 128;
    const int wm = (warp >> 2) * 64, wn = (warp & 3) * 32;

    const unsigned aoff = ((unsigned)((lane & 15) * H_LDW) + ((lane >> 4) << 3)) * 2;
    const unsigned boff = ((unsigned)((lane & 7) * H_LDW) + (((lane >> 3) & 1) << 3)) * 2;

    float acc[4][4][4];
#pragma unroll
    for (int mi = 0; mi < 4; mi++)
#pragma unroll
        for (int ni = 0; ni < 4; ni++)
#pragma unroll
            for (int q = 0; q < 4; q++) acc[mi][ni][q] = 0.f;

    auto load_stage = [&](int i) {
        const int s = i & 1;
        const unsigned sA = sbase + (unsigned)(s * 2 * H_TILEW * 2);
        const unsigned sB = sA + (unsigned)(H_TILEW * 2);
        const __half* Ap = A + (size_t)bm * lda + i * 64;
        const __half* Bp = Bt + (size_t)bn * K + i * 64;
#pragma unroll
        for (int j = 0; j < 4; j++) {
            int idx = tid + j * 256;
            int row = idx >> 3, segh = (idx & 7) << 3;
            cp16s(sA + row * 144 + segh * 2, Ap + (size_t)row * lda + segh);
            cp16s(sB + row * 144 + segh * 2, Bp + (size_t)row * K + segh);
        }
        CP_COMMIT();
    };

    const int KT = K / 64;
    load_stage(0);

    for (int kt = 0; kt < KT; kt++) {
        asm volatile("cp.async.wait_group 0;\n" ::: "memory");
        __syncthreads();
        if (kt + 1 < KT) load_stage(kt + 1);

        const int s = kt & 1;
        const unsigned aStage = sbase + (unsigned)(s * 2 * H_TILEW * 2);
        const unsigned bStage = aStage + (unsigned)(H_TILEW * 2);
#pragma unroll
        for (int ks = 0; ks < 4; ks++) {
            const unsigned kbb = (unsigned)(ks * 32);
            unsigned af[4][4], bf[4][2];
#pragma unroll
            for (int mi = 0; mi < 4; mi++)
                ldsm_x4(af[mi], aStage + (unsigned)((wm + mi * 16) * 144) + aoff + kbb);
#pragma unroll
            for (int ni = 0; ni < 4; ni++)
                ldsm_x2(bf[ni], bStage + (unsigned)((wn + ni * 8) * 144) + boff + kbb);
#pragma unroll
            for (int mi = 0; mi < 4; mi++)
#pragma unroll
                for (int ni = 0; ni < 4; ni++)
                    hmma(acc[mi][ni], af[mi], bf[ni][0], bf[ni][1]);
        }
    }

    const float al = (EPI == 1 || EPI == 3) ? alphap[0] : 0.f;
#pragma unroll
    for (int mi = 0; mi < 4; mi++) {
#pragma unroll
        for (int ni = 0; ni < 4; ni++) {
            int r0 = bm + wm + mi * 16 + g;
            int c  = bn + wn + ni * 8 + 2 * tq;
#pragma unroll
            for (int half = 0; half < 2; half++) {
                int r = r0 + half * 8;
                size_t off = (size_t)r * ldc + c;
                float v0 = acc[mi][ni][half * 2];
                float v1 = acc[mi][ni][half * 2 + 1];
                float o0, o1;
                if (EPI == 0) {
                    o0 = v0; o1 = v1;
                } else if (EPI == 1) {
                    o0 = resid[off] + al * v0;
                    o1 = resid[off + 1] + al * v1;
                } else if (EPI == 2) {
                    float u0 = v0 + bias[c], u1 = v1 + bias[c + 1];
                    o0 = 0.5f * u0 * (1.f + erff(u0 * 0.70710678118654752440f));
                    o1 = 0.5f * u1 * (1.f + erff(u1 * 0.70710678118654752440f));
                } else {
                    o0 = resid[off] + al * (v0 + bias[c]);
                    o1 = resid[off + 1] + al * (v1 + bias[c + 1]);
                }
                if (HOUT) {
                    *(__half2*)((__half*)Cv + off) = __floats2half2_rn(o0, o1);
                } else {
                    *(float2*)((float*)Cv + off) = make_float2(o0, o1);
                }
            }
        }
    }
}

// ---------------- batched QK^T (fp16 MMA + ldmatrix): S = Q @ K^T / 8 -> fp16 ---
__global__ __launch_bounds__(256)
void hqk(const __half* __restrict__ qkv, __half* __restrict__ S)
{
    __shared__ __half As[128][72];
    __shared__ __half Bs[128][72];

    const int bh = blockIdx.z, b = bh >> 4, h = bh & 15;
    const __half* Q  = qkv + (size_t)b * TT * (3 * DIM) + h * DK;
    const __half* Kp = qkv + (size_t)b * TT * (3 * DIM) + DIM + h * DK;
    __half* Sp = S + (size_t)bh * TT * TT;

    const int tid = threadIdx.x, lane = tid & 31, warp = tid >> 5;
    const int g = lane >> 2, tq = lane & 3;
    const int bm = blockIdx.y * 128, bn = blockIdx.x * 128;
    const int wm = (warp >> 2) * 64, wn = (warp & 3) * 32;

    const unsigned sA = (unsigned)__cvta_generic_to_shared(&As[0][0]);
    const unsigned sB = (unsigned)__cvta_generic_to_shared(&Bs[0][0]);
    const unsigned aoff = ((unsigned)((lane & 15) * 72) + ((lane >> 4) << 3)) * 2;
    const unsigned boff = ((unsigned)((lane & 7) * 72) + (((lane >> 3) & 1) << 3)) * 2;

    float acc[4][4][4];
#pragma unroll
    for (int mi = 0; mi < 4; mi++)
#pragma unroll
        for (int ni = 0; ni < 4; ni++)
#pragma unroll
            for (int q = 0; q < 4; q++) acc[mi][ni][q] = 0.f;

#pragma unroll
    for (int j = 0; j < 4; j++) {
        int idx = tid + j * 256;
        int m = idx >> 3, seg = (idx & 7) << 3;
        *(uint4*)&As[m][seg] = *(const uint4*)(Q  + (size_t)(bm + m) * (3 * DIM) + seg);
        *(uint4*)&Bs[m][seg] = *(const uint4*)(Kp + (size_t)(bn + m) * (3 * DIM) + seg);
    }
    __syncthreads();

#pragma unroll
    for (int ks = 0; ks < 4; ks++) {
        const unsigned kbb = (unsigned)(ks * 32);
        unsigned af[4][4], bf[4][2];
#pragma unroll
        for (int mi = 0; mi < 4; mi++)
            ldsm_x4(af[mi], sA + (unsigned)((wm + mi * 16) * 144) + aoff + kbb);
#pragma unroll
        for (int ni = 0; ni < 4; ni++)
            ldsm_x2(bf[ni], sB + (unsigned)((wn + ni * 8) * 144) + boff + kbb);
#pragma unroll
        for (int mi = 0; mi < 4; mi++)
#pragma unroll
            for (int ni = 0; ni < 4; ni++)
                hmma(acc[mi][ni], af[mi], bf[ni][0], bf[ni][1]);
    }

#pragma unroll
    for (int mi = 0; mi < 4; mi++)
#pragma unroll
        for (int ni = 0; ni < 4; ni++) {
            int r0 = bm + wm + mi * 16 + g;
            int c  = bn + wn + ni * 8 + 2 * tq;
#pragma unroll
            for (int half = 0; half < 2; half++) {
                size_t off = (size_t)(r0 + half * 8) * TT + c;
                *(__half2*)(Sp + off) = __floats2half2_rn(acc[mi][ni][half * 2] * 0.125f,
                                                          acc[mi][ni][half * 2 + 1] * 0.125f);
            }
        }
}

// ---------------- batched PV (fp16 MMA, BK=64 2-stage, 3 CTAs/SM) ---------------
#define PV_AW (128*72)
#define PV_BW (64*72)
#define PV_SMEM (2*(PV_AW+PV_BW)*2)

__global__ __launch_bounds__(256, 3)
void hpv(const __half* __restrict__ P, const __half* __restrict__ Vt,
         __half* __restrict__ attn_out)
{
    extern __shared__ __half smh[];
    const unsigned sbase = (unsigned)__cvta_generic_to_shared(smh);

    const int bh = blockIdx.y, b = bh >> 4, h = bh & 15;
    const __half* Pp = P + (size_t)bh * TT * TT;
    const __half* Vp = Vt + (size_t)bh * DK * TT;

    const int tid = threadIdx.x, lane = tid & 31, warp = tid >> 5;
    const int g = lane >> 2, tq = lane & 3;
    const int bm = blockIdx.x * 128;
    const int wm = (warp >> 1) * 32, wn = (warp & 1) * 32;

    const unsigned aoff = ((unsigned)((lane & 15) * 72) + ((lane >> 4) << 3)) * 2;
    const unsigned boff = ((unsigned)((lane & 7) * 72) + (((lane >> 3) & 1) << 3)) * 2;

    float acc[2][4][4];
#pragma unroll
    for (int mi = 0; mi < 2; mi++)
#pragma unroll
        for (int ni = 0; ni < 4; ni++)
#pragma unroll
            for (int q = 0; q < 4; q++) acc[mi][ni][q] = 0.f;

    auto load_stage = [&](int i) {
        const int s = i & 1;
        const unsigned sA = sbase + (unsigned)(s * (PV_AW + PV_BW) * 2);
        const unsigned sB = sA + (unsigned)(PV_AW * 2);
        const __half* Ap = Pp + i * 64;
        const __half* Bp = Vp + i * 64;
#pragma unroll
        for (int j = 0; j < 4; j++) {
            int idx = tid + j * 256;
            int row = idx >> 3, segh = (idx & 7) << 3;
            cp16s(sA + row * 144 + segh * 2, Ap + (size_t)(bm + row) * TT + segh);
        }
#pragma unroll
        for (int j = 0; j < 2; j++) {
            int idx = tid + j * 256;
            int row = idx >> 3, segh = (idx & 7) << 3;
            cp16s(sB + row * 144 + segh * 2, Bp + (size_t)row * TT + segh);
        }
        CP_COMMIT();
    };

    const int KT = TT / 64;
    load_stage(0);

    for (int kt = 0; kt < KT; kt++) {
        asm volatile("cp.async.wait_group 0;\n" ::: "memory");
        __syncthreads();
        if (kt + 1 < KT) load_stage(kt + 1);

        const int s = kt & 1;
        const unsigned aStage = sbase + (unsigned)(s * (PV_AW + PV_BW) * 2);
        const unsigned bStage = aStage + (unsigned)(PV_AW * 2);
#pragma unroll
        for (int ks = 0; ks < 4; ks++) {
            const unsigned kbb = (unsigned)(ks * 32);
            unsigned af[2][4], bf[4][2];
#pragma unroll
            for (int mi = 0; mi < 2; mi++)
                ldsm_x4(af[mi], aStage + (unsigned)((wm + mi * 16) * 144) + aoff + kbb);
#pragma unroll
            for (int ni = 0; ni < 4; ni++)
                ldsm_x2(bf[ni], bStage + (unsigned)((wn + ni * 8) * 144) + boff + kbb);
#pragma unroll
            for (int mi = 0; mi < 2; mi++)
#pragma unroll
                for (int ni = 0; ni < 4; ni++)
                    hmma(acc[mi][ni], af[mi], bf[ni][0], bf[ni][1]);
        }
    }

#pragma unroll
    for (int mi = 0; mi < 2; mi++)
#pragma unroll
        for (int ni = 0; ni < 4; ni++) {
            int r0 = bm + wm + mi * 16 + g;
            int c  = wn + ni * 8 + 2 * tq;
#pragma unroll
            for (int half = 0; half < 2; half++) {
                int r = r0 + half * 8;
                size_t off = (size_t)(b * TT + r) * DIM + h * DK + c;
                *(__half2*)(attn_out + off) =
                    __floats2half2_rn(acc[mi][ni][half * 2], acc[mi][ni][half * 2 + 1]);
            }
        }
}

// ---------------- fused dual softmax + exact top-64 (fp16 S, 16-bit radix) ------
__device__ __forceinline__ unsigned ordkey16(unsigned h)
{
    return (h & 0x8000u) ? (~h & 0xFFFFu) : (h | 0x8000u);
}
__device__ __forceinline__ float ordkey16_inv(unsigned k)
{
    unsigned short hb = (unsigned short)((k & 0x8000u) ? (k & 0x7FFFu) : (~k & 0xFFFFu));
    __half hv = __ushort_as_half(hb);
    return __half2float(hv);
}

__global__ __launch_bounds__(256)
void softmax_topk2(const __half* __restrict__ S, __half* __restrict__ P,
                   const float* __restrict__ alpha_head)
{
    __shared__ int   hist[256];
    __shared__ int   chunkeq[256];
    __shared__ int   chunkpre[256];
    __shared__ float rmax[8];
    __shared__ int   wri[8];
    __shared__ float wrf1[8], wrf2[8];
    __shared__ unsigned selb;
    __shared__ int   selc;

    const int tid = threadIdx.x, lane = tid & 31, w = tid >> 5;
    const int rowid = blockIdx.x;
    const int h = (rowid >> 11) & 15;
    const __half* row = S + (size_t)rowid * TT;
    __half* prow = P + (size_t)rowid * TT;

    uint4 pk = *(const uint4*)(row + tid * 8);
    unsigned hw[4] = {pk.x, pk.y, pk.z, pk.w};
    float v[8];
    unsigned u[8];
    float m = -3.4e38f;
#pragma unroll
    for (int i = 0; i < 4; i++) {
        unsigned lo = hw[i] & 0xFFFFu, hi = hw[i] >> 16;
        v[2 * i]     = __half2float(__ushort_as_half((unsigned short)lo));
        v[2 * i + 1] = __half2float(__ushort_as_half((unsigned short)hi));
        u[2 * i]     = ordkey16(lo);
        u[2 * i + 1] = ordkey16(hi);
    }
#pragma unroll
    for (int i = 0; i < 8; i++) m = fmaxf(m, v[i]);
#pragma unroll
    for (int o = 16; o > 0; o >>= 1) m = fmaxf(m, __shfl_xor_sync(0xFFFFFFFFu, m, o));
    if (lane == 0) rmax[w] = m;
    __syncthreads();
#pragma unroll
    for (int j = 0; j < 8; j++) m = fmaxf(m, rmax[j]);

    unsigned prefix = 0u, pmask = 0u;
    int kth = TOPK;
#pragma unroll
    for (int shift = 8; shift >= 0; shift -= 8) {
        hist[tid] = 0;
        __syncthreads();
#pragma unroll
        for (int i = 0; i < 8; i++)
            if ((u[i] & pmask) == prefix) atomicAdd(&hist[(u[i] >> shift) & 255], 1);
        __syncthreads();
        if (w == 0) {
            const int base = lane * 8;
            int hv[8], loc[8];
            int s = 0;
#pragma unroll
            for (int j = 7; j >= 0; j--) { hv[j] = hist[base + j]; s += hv[j]; loc[j] = s; }
            int suf = s;
#pragma unroll
            for (int o = 1; o < 32; o <<= 1) {
                int t = __shfl_down_sync(0xFFFFFFFFu, suf, o);
                if (lane + o < 32) suf += t;
            }
            const int higher = suf - s;
            int cand = -1, cabove = 0;
#pragma unroll
            for (int j = 7; j >= 0; j--) {
                int cum = higher + loc[j];
                if (cum >= kth) { cand = base + j; cabove = cum - hv[j]; break; }
            }
#pragma unroll
            for (int o = 16; o > 0; o >>= 1) {
                int oc = __shfl_xor_sync(0xFFFFFFFFu, cand, o);
                int oa = __shfl_xor_sync(0xFFFFFFFFu, cabove, o);
                if (oc > cand) { cand = oc; cabove = oa; }
            }
            if (lane == 0) { selb = (unsigned)cand; selc = cabove; }
        }
        __syncthreads();
        prefix |= selb << shift;
        pmask  |= 0xFFu << shift;
        kth    -= selc;
        __syncthreads();
    }
    const unsigned thr = prefix;

    float e[8];
    float sd = 0.f, sgt = 0.f;
    int cgt = 0, ceq = 0;
#pragma unroll
    for (int i = 0; i < 8; i++) {
        e[i] = __expf(v[i] - m);
        sd += e[i];
        if (u[i] > thr) { cgt++; sgt += e[i]; }
        else if (u[i] == thr) ceq++;
    }
    chunkeq[tid] = ceq;
#pragma unroll
    for (int o = 16; o > 0; o >>= 1) {
        sd  += __shfl_xor_sync(0xFFFFFFFFu, sd, o);
        sgt += __shfl_xor_sync(0xFFFFFFFFu, sgt, o);
        cgt += __shfl_xor_sync(0xFFFFFFFFu, cgt, o);
    }
    if (lane == 0) { wri[w] = cgt; wrf1[w] = sd; wrf2[w] = sgt; }
    __syncthreads();
    int n_gt = 0; float Zd = 0.f, Sgt = 0.f;
#pragma unroll
    for (int j = 0; j < 8; j++) { n_gt += wri[j]; Zd += wrf1[j]; Sgt += wrf2[j]; }

    const int need = TOPK - n_gt;
    const float ethr = __expf(ordkey16_inv(thr) - m);
    const float Zs = Sgt + (float)need * ethr;

    if (w == 0) {
        const int base = lane * 8;
        int c[8], loc[8];
        int ex = 0;
#pragma unroll
        for (int j = 0; j < 8; j++) { c[j] = chunkeq[base + j]; loc[j] = ex; ex += c[j]; }
        int acc = ex;
#pragma unroll
        for (int o = 1; o < 32; o <<= 1) {
            int t = __shfl_up_sync(0xFFFFFFFFu, acc, o);
            if (lane >= o) acc += t;
        }
        const int wex = acc - ex;
#pragma unroll
        for (int j = 0; j < 8; j++) chunkpre[base + j] = wex + loc[j];
    }
    __syncthreads();

    const float gate = 1.f / (1.f + __expf(-alpha_head[h]));
    const float cd = gate / Zd;
    const float cs = (1.f - gate) / Zs;

    int tierank = chunkpre[tid];
    __half hs[8];
#pragma unroll
    for (int i = 0; i < 8; i++) {
        bool inc;
        if (u[i] > thr) inc = true;
        else if (u[i] == thr) { inc = (tierank < need); tierank++; }
        else inc = false;
        hs[i] = __float2half_rn(e[i] * (cd + (inc ? cs : 0.f)));
    }
    *(uint4*)(prow + tid * 8) = *(uint4*)hs;
}

// ---------------- launch --------------------------------------------------------
extern "C" void kernel_launch(void* const* d_in, const int* in_sizes, int n_in,
                              void* d_out, int out_size)
{
    const float* x          = (const float*)d_in[0];
    const float* ln1_g      = (const float*)d_in[1];
    const float* ln1_b      = (const float*)d_in[2];
    const float* w_qkv      = (const float*)d_in[3];
    const float* alpha_head = (const float*)d_in[4];
    const float* w_out      = (const float*)d_in[5];
    const float* ln2_g      = (const float*)d_in[6];
    const float* ln2_b      = (const float*)d_in[7];
    const float* w1         = (const float*)d_in[8];
    const float* b1         = (const float*)d_in[9];
    const float* w2         = (const float*)d_in[10];
    const float* b2         = (const float*)d_in[11];
    const float* alpha      = (const float*)d_in[12];
    float* out = (float*)d_out;

    __half *xn, *qkv, *Sm, *P, *vt, *attn, *xn2, *hbuf, *wqkvT, *woutT, *w1T, *w2T;
    float *x1;
    cudaGetSymbolAddress((void**)&xn,    g_xn);
    cudaGetSymbolAddress((void**)&qkv,   g_qkv);
    cudaGetSymbolAddress((void**)&Sm,    g_S);
    cudaGetSymbolAddress((void**)&P,     g_P);
    cudaGetSymbolAddress((void**)&vt,    g_vt);
    cudaGetSymbolAddress((void**)&attn,  g_attn);
    cudaGetSymbolAddress((void**)&x1,    g_x1);
    cudaGetSymbolAddress((void**)&xn2,   g_xn2);
    cudaGetSymbolAddress((void**)&hbuf,  g_h);
    cudaGetSymbolAddress((void**)&wqkvT, g_wqkvT);
    cudaGetSymbolAddress((void**)&woutT, g_woutT);
    cudaGetSymbolAddress((void**)&w1T,   g_w1T);
    cudaGetSymbolAddress((void**)&w2T,   g_w2T);

    cudaFuncSetAttribute(hgemm<0>, cudaFuncAttributeMaxDynamicSharedMemorySize, H_SMEM);
    cudaFuncSetAttribute(hgemm<1>, cudaFuncAttributeMaxDynamicSharedMemorySize, H_SMEM);
    cudaFuncSetAttribute(hgemm<2>, cudaFuncAttributeMaxDynamicSharedMemorySize, H_SMEM);
    cudaFuncSetAttribute(hgemm<3>, cudaFuncAttributeMaxDynamicSharedMemorySize, H_SMEM);
    cudaFuncSetAttribute(hpv, cudaFuncAttributeMaxDynamicSharedMemorySize, PV_SMEM);

    trk<<<dim3(3*DIM/64, DIM/64), 256>>>(w_qkv, wqkvT, DIM, 3*DIM);
    trk<<<dim3(DIM/64,   DIM/64), 256>>>(w_out, woutT, DIM, DIM);
    trk<<<dim3(HID/64,   DIM/64), 256>>>(w1,    w1T,   DIM, HID);
    trk<<<dim3(DIM/64,   HID/64), 256>>>(w2,    w2T,   HID, DIM);

    ln_kernel<<<M_ROWS, 256>>>(x, ln1_g, ln1_b, xn);
    hgemm<0><<<dim3(3*DIM/128, M_ROWS/128), 256, H_SMEM>>>(
        DIM, xn, DIM, wqkvT, qkv, 3*DIM, nullptr, nullptr, nullptr);
    hqk<<<dim3(TT/128, TT/128, NBH), 256>>>(qkv, Sm);
    vtrans<<<dim3(TT/32, DK/32, NBH), dim3(32,8)>>>(qkv, vt);
    softmax_topk2<<<NBH*TT, 256>>>(Sm, P, alpha_head);
    hpv<<<dim3(TT/128, NBH), 256, PV_SMEM>>>(P, vt, attn);
    hgemm<1><<<dim3(DIM/128, M_ROWS/128), 256, H_SMEM>>>(
        DIM, attn, DIM, woutT, x1, DIM, nullptr, x, alpha);
    ln_kernel<<<M_ROWS, 256>>>(x1, ln2_g, ln2_b, xn2);
    hgemm<2><<<dim3(HID/128, M_ROWS/128), 256, H_SMEM>>>(
        DIM, xn2, DIM, w1T, hbuf, HID, b1, nullptr, nullptr);
    hgemm<3><<<dim3(DIM/128, M_ROWS/128), 256, H_SMEM>>>(
        HID, hbuf, HID, w2T, out, DIM, b2, x1, alpha);
}

// round 15
// speedup vs baseline: 1.0795x; 1.0183x over previous
#include <cuda_runtime.h>
#include <cuda_fp16.h>
#include <math.h>
#include <stdint.h>

// Problem constants
#define BB   2
#define TT   2048
#define DIM  1024
#define NH   16
#define DK   64
#define TOPK 64
#define HID  8192
#define M_ROWS (BB*TT)           // 4096
#define NBH  (BB*NH)             // 32

// ---------------- scratch ------------------------------------------------------
__device__ __half g_xn  [(size_t)M_ROWS * DIM];
__device__ __half g_qkv [(size_t)M_ROWS * 3 * DIM];
__device__ __half g_S   [(size_t)NBH * TT * TT];
__device__ __half g_P   [(size_t)NBH * TT * TT];
__device__ __half g_vt  [(size_t)NBH * DK * TT];
__device__ __half g_attn[(size_t)M_ROWS * DIM];
__device__ float  g_x1  [(size_t)M_ROWS * DIM];
__device__ __half g_xn2 [(size_t)M_ROWS * DIM];
__device__ __half g_h   [(size_t)M_ROWS * HID];
__device__ __half g_wqkvT[(size_t)3 * DIM * DIM];
__device__ __half g_woutT[(size_t)DIM * DIM];
__device__ __half g_w1T  [(size_t)HID * DIM];
__device__ __half g_w2T  [(size_t)DIM * HID];

// ---------------- helpers ------------------------------------------------------
__device__ __forceinline__ void hmma(float* c, const unsigned* a, const unsigned b0,
                                     const unsigned b1)
{
    asm volatile(
        "mma.sync.aligned.m16n8k16.row.col.f32.f16.f16.f32 "
        "{%0,%1,%2,%3},{%4,%5,%6,%7},{%8,%9},{%0,%1,%2,%3};\n"
        : "+f"(c[0]), "+f"(c[1]), "+f"(c[2]), "+f"(c[3])
        : "r"(a[0]), "r"(a[1]), "r"(a[2]), "r"(a[3]), "r"(b0), "r"(b1));
}
__device__ __forceinline__ void ldsm_x4(unsigned* r, unsigned saddr)
{
    asm volatile("ldmatrix.sync.aligned.m8n8.x4.shared.b16 {%0,%1,%2,%3}, [%4];"
                 : "=r"(r[0]), "=r"(r[1]), "=r"(r[2]), "=r"(r[3]) : "r"(saddr));
}
__device__ __forceinline__ void ldsm_x2(unsigned* r, unsigned saddr)
{
    asm volatile("ldmatrix.sync.aligned.m8n8.x2.shared.b16 {%0,%1}, [%2];"
                 : "=r"(r[0]), "=r"(r[1]) : "r"(saddr));
}
__device__ __forceinline__ void cp16s(unsigned saddr, const void* g)
{
    asm volatile("cp.async.cg.shared.global [%0], [%1], 16;\n" :: "r"(saddr), "l"(g));
}
#define CP_COMMIT() asm volatile("cp.async.commit_group;\n")

// ---------------- weight transpose fp32 -> half [C][R] (64x64 tiles) ------------
__global__ __launch_bounds__(256)
void trk(const float* __restrict__ src, __half* __restrict__ dst, int R, int C)
{
    __shared__ float t[64][65];
    const int c0 = blockIdx.x * 64, r0 = blockIdx.y * 64;
    const int tid = threadIdx.x;
#pragma unroll
    for (int j = 0; j < 4; j++) {
        int idx = tid + j * 256;
        int row = idx >> 4, c4 = (idx & 15) << 2;
        float4 v = *(const float4*)(src + (size_t)(r0 + row) * C + c0 + c4);
        t[row][c4 + 0] = v.x; t[row][c4 + 1] = v.y;
        t[row][c4 + 2] = v.z; t[row][c4 + 3] = v.w;
    }
    __syncthreads();
#pragma unroll
    for (int j = 0; j < 2; j++) {
        int idx = tid + j * 256;
        int drow = idx >> 3, seg = (idx & 7) << 3;
        __half hs[8];
#pragma unroll
        for (int k = 0; k < 8; k++)
            hs[k] = __float2half_rn(t[seg + k][drow]);
        *(uint4*)(dst + (size_t)(c0 + drow) * R + r0 + seg) = *(uint4*)hs;
    }
}

// ---------------- V transpose: qkv half -> vt[bh][d][t] -------------------------
__global__ __launch_bounds__(256)
void vtrans(const __half* __restrict__ qkv, __half* __restrict__ vt)
{
    __shared__ __half t[32][33];
    const int bh = blockIdx.z, b = bh >> 4, h = bh & 15;
    const int t0 = blockIdx.x * 32, d0 = blockIdx.y * 32;
    const int x = threadIdx.x, y = threadIdx.y;
#pragma unroll
    for (int j = 0; j < 32; j += 8)
        t[y + j][x] = qkv[(size_t)(b * TT + t0 + y + j) * (3 * DIM) + 2 * DIM + h * DK + d0 + x];
    __syncthreads();
#pragma unroll
    for (int j = 0; j < 32; j += 8)
        vt[((size_t)bh * DK + d0 + y + j) * TT + t0 + x] = t[x][y + j];
}

// ---------------- LayerNorm (half output, shuffle reductions) -------------------
__global__ __launch_bounds__(256)
void ln_kernel(const float* __restrict__ x, const float* __restrict__ g,
               const float* __restrict__ b, __half* __restrict__ o)
{
    const int rowbase = blockIdx.x * DIM;
    const int tid = threadIdx.x, lane = tid & 31, w = tid >> 5;
    float v[4];
    float s = 0.f, s2 = 0.f;
#pragma unroll
    for (int i = 0; i < 4; i++) {
        v[i] = x[rowbase + tid + i * 256];
        s  += v[i];
        s2 += v[i] * v[i];
    }
#pragma unroll
    for (int off = 16; off > 0; off >>= 1) {
        s  += __shfl_xor_sync(0xFFFFFFFFu, s, off);
        s2 += __shfl_xor_sync(0xFFFFFFFFu, s2, off);
    }
    __shared__ float ws[8], ws2[8];
    if (lane == 0) { ws[w] = s; ws2[w] = s2; }
    __syncthreads();
    float ts = 0.f, ts2 = 0.f;
#pragma unroll
    for (int j = 0; j < 8; j++) { ts += ws[j]; ts2 += ws2[j]; }
    const float mu   = ts * (1.f / DIM);
    const float var  = ts2 * (1.f / DIM) - mu * mu;
    const float rstd = rsqrtf(var + 1e-5f);
#pragma unroll
    for (int i = 0; i < 4; i++) {
        int c = tid + i * 256;
        o[rowbase + c] = __float2half_rn((v[i] - mu) * rstd * g[c] + b[c]);
    }
}

// ---------------- fp16 pipelined GEMM (R10: BK=64, 2-stage, warp 64x32) ---------
#define H_LDW 72
#define H_TILEW (128*H_LDW)
#define H_SMEM (2*2*H_TILEW*2)

template <int EPI>
__global__ __launch_bounds__(256, 2)
void hgemm(int K,
           const __half* __restrict__ A, int lda,
           const __half* __restrict__ Bt,
           void* __restrict__ Cv, int ldc,
           const float* __restrict__ bias,
           const float* __restrict__ resid,
           const float* __restrict__ alphap)
{
    constexpr bool HOUT = (EPI == 0 || EPI == 2);
    extern __shared__ __half smh[];
    const unsigned sbase = (unsigned)__cvta_generic_to_shared(smh);

    const int tid = threadIdx.x, lane = tid & 31, warp = tid >> 5;
    const int g = lane >> 2, tq = lane & 3;
    const int bm = blockIdx.y * 128, bn = blockIdx.x * 128;
    const int wm = (warp >> 2) * 64, wn = (warp & 3) * 32;

    const unsigned aoff = ((unsigned)((lane & 15) * H_LDW) + ((lane >> 4) << 3)) * 2;
    const unsigned boff = ((unsigned)((lane & 7) * H_LDW) + (((lane >> 3) & 1) << 3)) * 2;

    float acc[4][4][4];
#pragma unroll
    for (int mi = 0; mi < 4; mi++)
#pragma unroll
        for (int ni = 0; ni < 4; ni++)
#pragma unroll
            for (int q = 0; q < 4; q++) acc[mi][ni][q] = 0.f;

    auto load_stage = [&](int i) {
        const int s = i & 1;
        const unsigned sA = sbase + (unsigned)(s * 2 * H_TILEW * 2);
        const unsigned sB = sA + (unsigned)(H_TILEW * 2);
        const __half* Ap = A + (size_t)bm * lda + i * 64;
        const __half* Bp = Bt + (size_t)bn * K + i * 64;
#pragma unroll
        for (int j = 0; j < 4; j++) {
            int idx = tid + j * 256;
            int row = idx >> 3, segh = (idx & 7) << 3;
            cp16s(sA + row * 144 + segh * 2, Ap + (size_t)row * lda + segh);
            cp16s(sB + row * 144 + segh * 2, Bp + (size_t)row * K + segh);
        }
        CP_COMMIT();
    };

    const int KT = K / 64;
    load_stage(0);

    for (int kt = 0; kt < KT; kt++) {
        asm volatile("cp.async.wait_group 0;\n" ::: "memory");
        __syncthreads();
        if (kt + 1 < KT) load_stage(kt + 1);

        const int s = kt & 1;
        const unsigned aStage = sbase + (unsigned)(s * 2 * H_TILEW * 2);
        const unsigned bStage = aStage + (unsigned)(H_TILEW * 2);
#pragma unroll
        for (int ks = 0; ks < 4; ks++) {
            const unsigned kbb = (unsigned)(ks * 32);
            unsigned af[4][4], bf[4][2];
#pragma unroll
            for (int mi = 0; mi < 4; mi++)
                ldsm_x4(af[mi], aStage + (unsigned)((wm + mi * 16) * 144) + aoff + kbb);
#pragma unroll
            for (int ni = 0; ni < 4; ni++)
                ldsm_x2(bf[ni], bStage + (unsigned)((wn + ni * 8) * 144) + boff + kbb);
#pragma unroll
            for (int mi = 0; mi < 4; mi++)
#pragma unroll
                for (int ni = 0; ni < 4; ni++)
                    hmma(acc[mi][ni], af[mi], bf[ni][0], bf[ni][1]);
        }
    }

    const float al = (EPI == 1 || EPI == 3) ? alphap[0] : 0.f;
#pragma unroll
    for (int mi = 0; mi < 4; mi++) {
#pragma unroll
        for (int ni = 0; ni < 4; ni++) {
            int r0 = bm + wm + mi * 16 + g;
            int c  = bn + wn + ni * 8 + 2 * tq;
#pragma unroll
            for (int half = 0; half < 2; half++) {
                int r = r0 + half * 8;
                size_t off = (size_t)r * ldc + c;
                float v0 = acc[mi][ni][half * 2];
                float v1 = acc[mi][ni][half * 2 + 1];
                float o0, o1;
                if (EPI == 0) {
                    o0 = v0; o1 = v1;
                } else if (EPI == 1) {
                    o0 = resid[off] + al * v0;
                    o1 = resid[off + 1] + al * v1;
                } else if (EPI == 2) {
                    float u0 = v0 + bias[c], u1 = v1 + bias[c + 1];
                    o0 = 0.5f * u0 * (1.f + erff(u0 * 0.70710678118654752440f));
                    o1 = 0.5f * u1 * (1.f + erff(u1 * 0.70710678118654752440f));
                } else {
                    o0 = resid[off] + al * (v0 + bias[c]);
                    o1 = resid[off + 1] + al * (v1 + bias[c + 1]);
                }
                if (HOUT) {
                    *(__half2*)((__half*)Cv + off) = __floats2half2_rn(o0, o1);
                } else {
                    *(float2*)((float*)Cv + off) = make_float2(o0, o1);
                }
            }
        }
    }
}

// ---------------- batched QK^T (fp16 MMA + ldmatrix): S = Q @ K^T / 8 -> fp16 ---
__global__ __launch_bounds__(256)
void hqk(const __half* __restrict__ qkv, __half* __restrict__ S)
{
    __shared__ __half As[128][72];
    __shared__ __half Bs[128][72];

    const int bh = blockIdx.z, b = bh >> 4, h = bh & 15;
    const __half* Q  = qkv + (size_t)b * TT * (3 * DIM) + h * DK;
    const __half* Kp = qkv + (size_t)b * TT * (3 * DIM) + DIM + h * DK;
    __half* Sp = S + (size_t)bh * TT * TT;

    const int tid = threadIdx.x, lane = tid & 31, warp = tid >> 5;
    const int g = lane >> 2, tq = lane & 3;
    const int bm = blockIdx.y * 128, bn = blockIdx.x * 128;
    const int wm = (warp >> 2) * 64, wn = (warp & 3) * 32;

    const unsigned sA = (unsigned)__cvta_generic_to_shared(&As[0][0]);
    const unsigned sB = (unsigned)__cvta_generic_to_shared(&Bs[0][0]);
    const unsigned aoff = ((unsigned)((lane & 15) * 72) + ((lane >> 4) << 3)) * 2;
    const unsigned boff = ((unsigned)((lane & 7) * 72) + (((lane >> 3) & 1) << 3)) * 2;

    float acc[4][4][4];
#pragma unroll
    for (int mi = 0; mi < 4; mi++)
#pragma unroll
        for (int ni = 0; ni < 4; ni++)
#pragma unroll
            for (int q = 0; q < 4; q++) acc[mi][ni][q] = 0.f;

#pragma unroll
    for (int j = 0; j < 4; j++) {
        int idx = tid + j * 256;
        int m = idx >> 3, seg = (idx & 7) << 3;
        *(uint4*)&As[m][seg] = *(const uint4*)(Q  + (size_t)(bm + m) * (3 * DIM) + seg);
        *(uint4*)&Bs[m][seg] = *(const uint4*)(Kp + (size_t)(bn + m) * (3 * DIM) + seg);
    }
    __syncthreads();

#pragma unroll
    for (int ks = 0; ks < 4; ks++) {
        const unsigned kbb = (unsigned)(ks * 32);
        unsigned af[4][4], bf[4][2];
#pragma unroll
        for (int mi = 0; mi < 4; mi++)
            ldsm_x4(af[mi], sA + (unsigned)((wm + mi * 16) * 144) + aoff + kbb);
#pragma unroll
        for (int ni = 0; ni < 4; ni++)
            ldsm_x2(bf[ni], sB + (unsigned)((wn + ni * 8) * 144) + boff + kbb);
#pragma unroll
        for (int mi = 0; mi < 4; mi++)
#pragma unroll
            for (int ni = 0; ni < 4; ni++)
                hmma(acc[mi][ni], af[mi], bf[ni][0], bf[ni][1]);
    }

#pragma unroll
    for (int mi = 0; mi < 4; mi++)
#pragma unroll
        for (int ni = 0; ni < 4; ni++) {
            int r0 = bm + wm + mi * 16 + g;
            int c  = bn + wn + ni * 8 + 2 * tq;
#pragma unroll
            for (int half = 0; half < 2; half++) {
                size_t off = (size_t)(r0 + half * 8) * TT + c;
                *(__half2*)(Sp + off) = __floats2half2_rn(acc[mi][ni][half * 2] * 0.125f,
                                                          acc[mi][ni][half * 2 + 1] * 0.125f);
            }
        }
}

// ---------------- batched PV (fp16 MMA, BK=64 2-stage, 3 CTAs/SM) ---------------
#define PV_AW (128*72)
#define PV_BW (64*72)
#define PV_SMEM (2*(PV_AW+PV_BW)*2)

__global__ __launch_bounds__(256, 3)
void hpv(const __half* __restrict__ P, const __half* __restrict__ Vt,
         __half* __restrict__ attn_out)
{
    extern __shared__ __half smh[];
    const unsigned sbase = (unsigned)__cvta_generic_to_shared(smh);

    const int bh = blockIdx.y, b = bh >> 4, h = bh & 15;
    const __half* Pp = P + (size_t)bh * TT * TT;
    const __half* Vp = Vt + (size_t)bh * DK * TT;

    const int tid = threadIdx.x, lane = tid & 31, warp = tid >> 5;
    const int g = lane >> 2, tq = lane & 3;
    const int bm = blockIdx.x * 128;
    const int wm = (warp >> 1) * 32, wn = (warp & 1) * 32;

    const unsigned aoff = ((unsigned)((lane & 15) * 72) + ((lane >> 4) << 3)) * 2;
    const unsigned boff = ((unsigned)((lane & 7) * 72) + (((lane >> 3) & 1) << 3)) * 2;

    float acc[2][4][4];
#pragma unroll
    for (int mi = 0; mi < 2; mi++)
#pragma unroll
        for (int ni = 0; ni < 4; ni++)
#pragma unroll
            for (int q = 0; q < 4; q++) acc[mi][ni][q] = 0.f;

    auto load_stage = [&](int i) {
        const int s = i & 1;
        const unsigned sA = sbase + (unsigned)(s * (PV_AW + PV_BW) * 2);
        const unsigned sB = sA + (unsigned)(PV_AW * 2);
        const __half* Ap = Pp + i * 64;
        const __half* Bp = Vp + i * 64;
#pragma unroll
        for (int j = 0; j < 4; j++) {
            int idx = tid + j * 256;
            int row = idx >> 3, segh = (idx & 7) << 3;
            cp16s(sA + row * 144 + segh * 2, Ap + (size_t)(bm + row) * TT + segh);
        }
#pragma unroll
        for (int j = 0; j < 2; j++) {
            int idx = tid + j * 256;
            int row = idx >> 3, segh = (idx & 7) << 3;
            cp16s(sB + row * 144 + segh * 2, Bp + (size_t)row * TT + segh);
        }
        CP_COMMIT();
    };

    const int KT = TT / 64;
    load_stage(0);

    for (int kt = 0; kt < KT; kt++) {
        asm volatile("cp.async.wait_group 0;\n" ::: "memory");
        __syncthreads();
        if (kt + 1 < KT) load_stage(kt + 1);

        const int s = kt & 1;
        const unsigned aStage = sbase + (unsigned)(s * (PV_AW + PV_BW) * 2);
        const unsigned bStage = aStage + (unsigned)(PV_AW * 2);
#pragma unroll
        for (int ks = 0; ks < 4; ks++) {
            const unsigned kbb = (unsigned)(ks * 32);
            unsigned af[2][4], bf[4][2];
#pragma unroll
            for (int mi = 0; mi < 2; mi++)
                ldsm_x4(af[mi], aStage + (unsigned)((wm + mi * 16) * 144) + aoff + kbb);
#pragma unroll
            for (int ni = 0; ni < 4; ni++)
                ldsm_x2(bf[ni], bStage + (unsigned)((wn + ni * 8) * 144) + boff + kbb);
#pragma unroll
            for (int mi = 0; mi < 2; mi++)
#pragma unroll
                for (int ni = 0; ni < 4; ni++)
                    hmma(acc[mi][ni], af[mi], bf[ni][0], bf[ni][1]);
        }
    }

#pragma unroll
    for (int mi = 0; mi < 2; mi++)
#pragma unroll
        for (int ni = 0; ni < 4; ni++) {
            int r0 = bm + wm + mi * 16 + g;
            int c  = wn + ni * 8 + 2 * tq;
#pragma unroll
            for (int half = 0; half < 2; half++) {
                int r = r0 + half * 8;
                size_t off = (size_t)(b * TT + r) * DIM + h * DK + c;
                *(__half2*)(attn_out + off) =
                    __floats2half2_rn(acc[mi][ni][half * 2], acc[mi][ni][half * 2 + 1]);
            }
        }
}

// ---------------- fused dual softmax + exact top-64 (fp16 S, 16-bit radix) ------
__device__ __forceinline__ unsigned ordkey16(unsigned h)
{
    return (h & 0x8000u) ? (~h & 0xFFFFu) : (h | 0x8000u);
}
__device__ __forceinline__ float ordkey16_inv(unsigned k)
{
    unsigned short hb = (unsigned short)((k & 0x8000u) ? (k & 0x7FFFu) : (~k & 0xFFFFu));
    __half hv = __ushort_as_half(hb);
    return __half2float(hv);
}

__global__ __launch_bounds__(256)
void softmax_topk2(const __half* __restrict__ S, __half* __restrict__ P,
                   const float* __restrict__ alpha_head)
{
    __shared__ int   hist[256];
    __shared__ int   chunkeq[256];
    __shared__ int   chunkpre[256];
    __shared__ float rmax[8];
    __shared__ int   wri[8];
    __shared__ float wrf1[8], wrf2[8];
    __shared__ unsigned selb;
    __shared__ int   selc;

    const int tid = threadIdx.x, lane = tid & 31, w = tid >> 5;
    const int rowid = blockIdx.x;
    const int h = (rowid >> 11) & 15;
    const __half* row = S + (size_t)rowid * TT;
    __half* prow = P + (size_t)rowid * TT;

    uint4 pk = *(const uint4*)(row + tid * 8);
    unsigned hw[4] = {pk.x, pk.y, pk.z, pk.w};
    float v[8];
    unsigned u[8];
    float m = -3.4e38f;
#pragma unroll
    for (int i = 0; i < 4; i++) {
        unsigned lo = hw[i] & 0xFFFFu, hi = hw[i] >> 16;
        v[2 * i]     = __half2float(__ushort_as_half((unsigned short)lo));
        v[2 * i + 1] = __half2float(__ushort_as_half((unsigned short)hi));
        u[2 * i]     = ordkey16(lo);
        u[2 * i + 1] = ordkey16(hi);
    }
#pragma unroll
    for (int i = 0; i < 8; i++) m = fmaxf(m, v[i]);
#pragma unroll
    for (int o = 16; o > 0; o >>= 1) m = fmaxf(m, __shfl_xor_sync(0xFFFFFFFFu, m, o));
    if (lane == 0) rmax[w] = m;
    __syncthreads();
#pragma unroll
    for (int j = 0; j < 8; j++) m = fmaxf(m, rmax[j]);

    unsigned prefix = 0u, pmask = 0u;
    int kth = TOPK;
#pragma unroll
    for (int shift = 8; shift >= 0; shift -= 8) {
        hist[tid] = 0;
        __syncthreads();
#pragma unroll
        for (int i = 0; i < 8; i++)
            if ((u[i] & pmask) == prefix) atomicAdd(&hist[(u[i] >> shift) & 255], 1);
        __syncthreads();
        if (w == 0) {
            const int base = lane * 8;
            int hv[8], loc[8];
            int s = 0;
#pragma unroll
            for (int j = 7; j >= 0; j--) { hv[j] = hist[base + j]; s += hv[j]; loc[j] = s; }
            int suf = s;
#pragma unroll
            for (int o = 1; o < 32; o <<= 1) {
                int t = __shfl_down_sync(0xFFFFFFFFu, suf, o);
                if (lane + o < 32) suf += t;
            }
            const int higher = suf - s;
            int cand = -1, cabove = 0;
#pragma unroll
            for (int j = 7; j >= 0; j--) {
                int cum = higher + loc[j];
                if (cum >= kth) { cand = base + j; cabove = cum - hv[j]; break; }
            }
#pragma unroll
            for (int o = 16; o > 0; o >>= 1) {
                int oc = __shfl_xor_sync(0xFFFFFFFFu, cand, o);
                int oa = __shfl_xor_sync(0xFFFFFFFFu, cabove, o);
                if (oc > cand) { cand = oc; cabove = oa; }
            }
            if (lane == 0) { selb = (unsigned)cand; selc = cabove; }
        }
        __syncthreads();
        prefix |= selb << shift;
        pmask  |= 0xFFu << shift;
        kth    -= selc;
        __syncthreads();
    }
    const unsigned thr = prefix;

    float e[8];
    float sd = 0.f, sgt = 0.f;
    int cgt = 0, ceq = 0;
#pragma unroll
    for (int i = 0; i < 8; i++) {
        e[i] = __expf(v[i] - m);
        sd += e[i];
        if (u[i] > thr) { cgt++; sgt += e[i]; }
        else if (u[i] == thr) ceq++;
    }
    chunkeq[tid] = ceq;
#pragma unroll
    for (int o = 16; o > 0; o >>= 1) {
        sd  += __shfl_xor_sync(0xFFFFFFFFu, sd, o);
        sgt += __shfl_xor_sync(0xFFFFFFFFu, sgt, o);
        cgt += __shfl_xor_sync(0xFFFFFFFFu, cgt, o);
    }
    if (lane == 0) { wri[w] = cgt; wrf1[w] = sd; wrf2[w] = sgt; }
    __syncthreads();
    int n_gt = 0; float Zd = 0.f, Sgt = 0.f;
#pragma unroll
    for (int j = 0; j < 8; j++) { n_gt += wri[j]; Zd += wrf1[j]; Sgt += wrf2[j]; }

    const int need = TOPK - n_gt;
    const float ethr = __expf(ordkey16_inv(thr) - m);
    const float Zs = Sgt + (float)need * ethr;

    if (w == 0) {
        const int base = lane * 8;
        int c[8], loc[8];
        int ex = 0;
#pragma unroll
        for (int j = 0; j < 8; j++) { c[j] = chunkeq[base + j]; loc[j] = ex; ex += c[j]; }
        int acc = ex;
#pragma unroll
        for (int o = 1; o < 32; o <<= 1) {
            int t = __shfl_up_sync(0xFFFFFFFFu, acc, o);
            if (lane >= o) acc += t;
        }
        const int wex = acc - ex;
#pragma unroll
        for (int j = 0; j < 8; j++) chunkpre[base + j] = wex + loc[j];
    }
    __syncthreads();

    const float gate = 1.f / (1.f + __expf(-alpha_head[h]));
    const float cd = gate / Zd;
    const float cs = (1.f - gate) / Zs;

    int tierank = chunkpre[tid];
    __half hs[8];
#pragma unroll
    for (int i = 0; i < 8; i++) {
        bool inc;
        if (u[i] > thr) inc = true;
        else if (u[i] == thr) { inc = (tierank < need); tierank++; }
        else inc = false;
        hs[i] = __float2half_rn(e[i] * (cd + (inc ? cs : 0.f)));
    }
    *(uint4*)(prow + tid * 8) = *(uint4*)hs;
}

// ---------------- launch (dual-stream fork/join, graph-capturable) ---------------
extern "C" void kernel_launch(void* const* d_in, const int* in_sizes, int n_in,
                              void* d_out, int out_size)
{
    const float* x          = (const float*)d_in[0];
    const float* ln1_g      = (const float*)d_in[1];
    const float* ln1_b      = (const float*)d_in[2];
    const float* w_qkv      = (const float*)d_in[3];
    const float* alpha_head = (const float*)d_in[4];
    const float* w_out      = (const float*)d_in[5];
    const float* ln2_g      = (const float*)d_in[6];
    const float* ln2_b      = (const float*)d_in[7];
    const float* w1         = (const float*)d_in[8];
    const float* b1         = (const float*)d_in[9];
    const float* w2         = (const float*)d_in[10];
    const float* b2         = (const float*)d_in[11];
    const float* alpha      = (const float*)d_in[12];
    float* out = (float*)d_out;

    __half *xn, *qkv, *Sm, *P, *vt, *attn, *xn2, *hbuf, *wqkvT, *woutT, *w1T, *w2T;
    float *x1;
    cudaGetSymbolAddress((void**)&xn,    g_xn);
    cudaGetSymbolAddress((void**)&qkv,   g_qkv);
    cudaGetSymbolAddress((void**)&Sm,    g_S);
    cudaGetSymbolAddress((void**)&P,     g_P);
    cudaGetSymbolAddress((void**)&vt,    g_vt);
    cudaGetSymbolAddress((void**)&attn,  g_attn);
    cudaGetSymbolAddress((void**)&x1,    g_x1);
    cudaGetSymbolAddress((void**)&xn2,   g_xn2);
    cudaGetSymbolAddress((void**)&hbuf,  g_h);
    cudaGetSymbolAddress((void**)&wqkvT, g_wqkvT);
    cudaGetSymbolAddress((void**)&woutT, g_woutT);
    cudaGetSymbolAddress((void**)&w1T,   g_w1T);
    cudaGetSymbolAddress((void**)&w2T,   g_w2T);

    cudaFuncSetAttribute(hgemm<0>, cudaFuncAttributeMaxDynamicSharedMemorySize, H_SMEM);
    cudaFuncSetAttribute(hgemm<1>, cudaFuncAttributeMaxDynamicSharedMemorySize, H_SMEM);
    cudaFuncSetAttribute(hgemm<2>, cudaFuncAttributeMaxDynamicSharedMemorySize, H_SMEM);
    cudaFuncSetAttribute(hgemm<3>, cudaFuncAttributeMaxDynamicSharedMemorySize, H_SMEM);
    cudaFuncSetAttribute(hpv, cudaFuncAttributeMaxDynamicSharedMemorySize, PV_SMEM);

    // side stream + events (host-side objects; no device memory). Created per call
    // and intentionally not destroyed so graph-referenced objects stay alive.
    cudaStream_t s2;
    cudaStreamCreateWithFlags(&s2, cudaStreamNonBlocking);
    cudaEvent_t ev0, evQ, evG, evV;
    cudaEventCreateWithFlags(&ev0, cudaEventDisableTiming);
    cudaEventCreateWithFlags(&evQ, cudaEventDisableTiming);
    cudaEventCreateWithFlags(&evG, cudaEventDisableTiming);
    cudaEventCreateWithFlags(&evV, cudaEventDisableTiming);

    // fork side stream from the main (default) stream
    cudaEventRecord(ev0, 0);
    cudaStreamWaitEvent(s2, ev0, 0);

    // side stream: weight transposes (wqkvT first — needed earliest)
    trk<<<dim3(3*DIM/64, DIM/64), 256, 0, s2>>>(w_qkv, wqkvT, DIM, 3*DIM);
    cudaEventRecord(evQ, s2);
    trk<<<dim3(DIM/64,   DIM/64), 256, 0, s2>>>(w_out, woutT, DIM, DIM);
    trk<<<dim3(HID/64,   DIM/64), 256, 0, s2>>>(w1,    w1T,   DIM, HID);
    trk<<<dim3(DIM/64,   HID/64), 256, 0, s2>>>(w2,    w2T,   HID, DIM);

    // main stream: LN1 runs concurrent with trk(wqkv)
    ln_kernel<<<M_ROWS, 256>>>(x, ln1_g, ln1_b, xn);
    cudaStreamWaitEvent(0, evQ, 0);
    hgemm<0><<<dim3(3*DIM/128, M_ROWS/128), 256, H_SMEM>>>(
        DIM, xn, DIM, wqkvT, qkv, 3*DIM, nullptr, nullptr, nullptr);
    cudaEventRecord(evG, 0);

    // side stream: vtrans after qkv is ready (concurrent with hqk/softmax)
    cudaStreamWaitEvent(s2, evG, 0);
    vtrans<<<dim3(TT/32, DK/32, NBH), dim3(32,8), 0, s2>>>(qkv, vt);
    cudaEventRecord(evV, s2);

    // main stream
    hqk<<<dim3(TT/128, TT/128, NBH), 256>>>(qkv, Sm);
    softmax_topk2<<<NBH*TT, 256>>>(Sm, P, alpha_head);
    cudaStreamWaitEvent(0, evV, 0);     // join: vt + all weight transposes done
    hpv<<<dim3(TT/128, NBH), 256, PV_SMEM>>>(P, vt, attn);
    hgemm<1><<<dim3(DIM/128, M_ROWS/128), 256, H_SMEM>>>(
        DIM, attn, DIM, woutT, x1, DIM, nullptr, x, alpha);
    ln_kernel<<<M_ROWS, 256>>>(x1, ln2_g, ln2_b, xn2);
    hgemm<2><<<dim3(HID/128, M_ROWS/128), 256, H_SMEM>>>(
        DIM, xn2, DIM, w1T, hbuf, HID, b1, nullptr, nullptr);
    hgemm<3><<<dim3(DIM/128, M_ROWS/128), 256, H_SMEM>>>(
        HID, hbuf, HID, w2T, out, DIM, b2, x1, alpha);
}